// round 10
// baseline (speedup 1.0000x reference)
#include <cuda_runtime.h>
#include <cuda_fp16.h>

#define B_SZ    512
#define FEATS   30
#define NNZ     (B_SZ * FEATS)
#define FT_OUT  512
#define N_FEAT  40960
#define N_VFEAT 640
#define HALF_C  (N_FEAT / 2)    // 20480

// Packed indices, feature-major: g_packed[f*B + b] = stm_col | (nstm_col<<16)
__device__ unsigned g_packed[NNZ];
__device__ __half   g_vals[NNZ];          // values, feature-major, fp16
// Partial outputs, [k][b] layout -> coalesced stores and reads. 1 MB.
__device__ float    g_partial[FT_OUT * B_SZ];

// Dynamic smem: __half sft[N_FEAT] (fused ft+fft table), __half sfft[N_VFEAT]
#define SMEM_BYTES ((N_FEAT + N_VFEAT) * 2)

static __device__ __forceinline__ unsigned h2u(__half2 h) {
    return *reinterpret_cast<unsigned*>(&h);
}

// ---------------------------------------------------------------------------
// Kernel 0: prepass. Pack cols into u32, values into fp16, feature-major.
// Triggers PDL completion immediately so the main kernel streams concurrently.
// ---------------------------------------------------------------------------
__global__ void __launch_bounds__(256) pack_idx_kernel(
    const int*   __restrict__ stm_idx,    // [2, NNZ]; cols at offset NNZ
    const int*   __restrict__ nstm_idx,   // [2, NNZ]
    const float* __restrict__ values)     // [NNZ]
{
    cudaTriggerProgrammaticLaunchCompletion();

    const int e = blockIdx.x * 256 + threadIdx.x;
    if (e >= NNZ) return;
    const int b = e / FEATS;
    const int f = e % FEATS;
    const unsigned cs = (unsigned)stm_idx [NNZ + e];
    const unsigned cn = (unsigned)nstm_idx[NNZ + e];
    const int dst = f * B_SZ + b;
    g_packed[dst] = cs | (cn << 16);
    g_vals[dst]   = __float2half(values[e]);
}

// ---------------------------------------------------------------------------
// Kernel 1: one CTA per output unit k (512 CTAs, 512 threads, 2 CTAs/SM).
// Phase A : fft_w row k -> smem fp16.
// Phase B1: ALL threads stream ft_w cols [0, HALF_C), fusing fft -> sft.
// Overlap : warps 0-7 stream cols [HALF_C, N_FEAT) WHILE warps 8-15 compute
//           all lookups with col < HALF_C (2 batch rows per compute thread).
// Phase C2: warps 8-15 compute lookups with col >= HALF_C, then epilogue.
// ---------------------------------------------------------------------------
__global__ void __launch_bounds__(512, 2) halfkp_k_kernel(
    const float* __restrict__ ft_w,      // [512, 40960]
    const float* __restrict__ ft_b,      // [512]
    const float* __restrict__ fft_w,     // [512, 640]
    const float* __restrict__ fft_b,     // [512]
    const float* __restrict__ out_w)     // [1, 1024]
{
    cudaTriggerProgrammaticLaunchCompletion();   // let reduce kernel launch

    extern __shared__ char smem_raw[];
    __half* sft  = reinterpret_cast<__half*>(smem_raw);            // [N_FEAT]
    __half* sfft = sft + N_FEAT;                                   // [N_VFEAT]

    const int k = blockIdx.x;
    const int t = threadIdx.x;

    // ---- Phase A: fft_w row k -> smem fp16 ----
    if (t < N_VFEAT / 4) {   // 160 threads, one float4 each
        float4 a = __ldg(reinterpret_cast<const float4*>(
                             fft_w + (size_t)k * N_VFEAT) + t);
        uint2 p = make_uint2(h2u(__floats2half2_rn(a.x, a.y)),
                             h2u(__floats2half2_rn(a.z, a.w)));
        reinterpret_cast<uint2*>(sfft)[t] = p;
    }
    __syncthreads();

    const float4* row = reinterpret_cast<const float4*>(ft_w + (size_t)k * N_FEAT);

    // ---- Phase B1: all 512 threads stream lower half [0, HALF_C) ----
    {
        // m = (4t + 2048 i) % 640 has period 5 in i -> register-cached pairs
        __half2 fA[5], fB[5];
        #pragma unroll
        for (int j = 0; j < 5; j++) {
            const int m = (4 * t + 2048 * j) % N_VFEAT;
            fA[j] = *reinterpret_cast<const __half2*>(sfft + m);
            fB[j] = *reinterpret_cast<const __half2*>(sfft + m + 2);
        }
        #pragma unroll
        for (int i = 0; i < HALF_C / 4 / 512; i++) {   // 10 iterations
            const int idx = t + i * 512;
            const int c   = idx * 4;
            const int j   = i % 5;
            float4 a = __ldg(row + idx);
            __half2 h01 = __hadd2(__floats2half2_rn(a.x, a.y), fA[j]);
            __half2 h23 = __hadd2(__floats2half2_rn(a.z, a.w), fB[j]);
            *reinterpret_cast<uint2*>(sft + c) = make_uint2(h2u(h01), h2u(h23));
        }
    }
    __syncthreads();

    if (t < 256) {
        // ---- Streamer warps 0-7: upper half [HALF_C, N_FEAT) ----
        #pragma unroll 4
        for (int i = 0; i < HALF_C / 4 / 256; i++) {   // 20 iterations
            const int idx = t + i * 256;
            const int c   = HALF_C + idx * 4;
            const int m   = c % N_VFEAT;               // multiple of 4
            float4 a = __ldg(row + HALF_C / 4 + idx);
            __half2 f01 = *reinterpret_cast<const __half2*>(sfft + m);
            __half2 f23 = *reinterpret_cast<const __half2*>(sfft + m + 2);
            __half2 h01 = __hadd2(__floats2half2_rn(a.x, a.y), f01);
            __half2 h23 = __hadd2(__floats2half2_rn(a.z, a.w), f23);
            *reinterpret_cast<uint2*>(sft + c) = make_uint2(h2u(h01), h2u(h23));
        }
        __syncthreads();    // barrier 2
        // streamers done; exit after final (no more barriers below)
    } else {
        // ---- Compute warps 8-15: two rows each (ct and ct+256) ----
        const int ct = t - 256;

        // PDL: packed index data must be ready before first use.
        cudaGridDependencySynchronize();

        float acc[2][2] = {{0.f, 0.f}, {0.f, 0.f}};    // [row][stm/nstm]

        // --- C1: lower-half lookups (table [0, HALF_C) is ready) ---
        #pragma unroll
        for (int rr = 0; rr < 2; rr++) {
            const int r = ct + rr * 256;
            #pragma unroll
            for (int ch = 0; ch < 3; ch++) {
                unsigned p[10]; __half v[10];
                #pragma unroll
                for (int f = 0; f < 10; f++) {
                    const int idx = (ch * 10 + f) * B_SZ + r;
                    p[f] = __ldg(g_packed + idx);
                    v[f] = g_vals[idx];
                }
                #pragma unroll
                for (int f = 0; f < 10; f++) {
                    const float vf = __half2float(v[f]);
                    const unsigned cs = p[f] & 0xFFFFu;
                    const unsigned cn = p[f] >> 16;
                    if (cs < HALF_C)
                        acc[rr][0] = fmaf(vf, __half2float(sft[cs]), acc[rr][0]);
                    if (cn < HALF_C)
                        acc[rr][1] = fmaf(vf, __half2float(sft[cn]), acc[rr][1]);
                }
            }
        }

        __syncthreads();    // barrier 2: upper half of table now ready

        // --- C2: upper-half lookups ---
        #pragma unroll
        for (int rr = 0; rr < 2; rr++) {
            const int r = ct + rr * 256;
            #pragma unroll
            for (int ch = 0; ch < 3; ch++) {
                unsigned p[10]; __half v[10];
                #pragma unroll
                for (int f = 0; f < 10; f++) {
                    const int idx = (ch * 10 + f) * B_SZ + r;
                    p[f] = __ldg(g_packed + idx);
                    v[f] = g_vals[idx];
                }
                #pragma unroll
                for (int f = 0; f < 10; f++) {
                    const float vf = __half2float(v[f]);
                    const unsigned cs = p[f] & 0xFFFFu;
                    const unsigned cn = p[f] >> 16;
                    if (cs >= HALF_C)
                        acc[rr][0] = fmaf(vf, __half2float(sft[cs]), acc[rr][0]);
                    if (cn >= HALF_C)
                        acc[rr][1] = fmaf(vf, __half2float(sft[cn]), acc[rr][1]);
                }
            }
        }

        // --- Epilogue: bias + clip + out_w partial, coalesced stores ---
        const float bias = __ldg(ft_b + k) + __ldg(fft_b + k);
        const float ws   = __ldg(out_w + k);
        const float wn   = __ldg(out_w + FT_OUT + k);

        #pragma unroll
        for (int rr = 0; rr < 2; rr++) {
            const float part = ws * __saturatef(acc[rr][0] + bias)
                             + wn * __saturatef(acc[rr][1] + bias);
            g_partial[k * B_SZ + ct + rr * 256] = part;
        }
    }
}

// ---------------------------------------------------------------------------
// Kernel 2: sum the 512 k-partials per batch row ([k][b], coalesced along b),
// add out_b, sigmoid. Deterministic fixed-order summation. PDL-parked.
// ---------------------------------------------------------------------------
__global__ void __launch_bounds__(256) halfkp_reduce_kernel(
    const float* __restrict__ out_b,
    float*       __restrict__ out)       // [512]
{
    const int tx = threadIdx.x & 31;     // batch lane
    const int ty = threadIdx.x >> 5;     // k group (0..7), 64 k's each
    const int b  = blockIdx.x * 32 + tx;

    cudaGridDependencySynchronize();     // wait for main kernel's g_partial

    float s = 0.f;
    #pragma unroll 8
    for (int i = 0; i < FT_OUT / 8; i++)
        s += g_partial[(ty * (FT_OUT / 8) + i) * B_SZ + b];

    __shared__ float red[8][33];
    red[ty][tx] = s;
    __syncthreads();

    if (ty == 0) {
        float tot = __ldg(out_b);
        #pragma unroll
        for (int j = 0; j < 8; j++) tot += red[j][tx];
        out[b] = 1.0f / (1.0f + expf(-tot));
    }
}

// ---------------------------------------------------------------------------
extern "C" void kernel_launch(void* const* d_in, const int* in_sizes, int n_in,
                              void* d_out, int out_size) {
    const int*   stm_idx  = (const int*)  d_in[0];
    const int*   nstm_idx = (const int*)  d_in[1];
    const float* values   = (const float*)d_in[2];
    const float* ft_w     = (const float*)d_in[3];
    const float* ft_b     = (const float*)d_in[4];
    const float* fft_w    = (const float*)d_in[5];
    const float* fft_b    = (const float*)d_in[6];
    const float* out_w    = (const float*)d_in[7];
    const float* out_b    = (const float*)d_in[8];
    float*       out      = (float*)d_out;

    (void)in_sizes; (void)n_in; (void)out_size;

    cudaFuncSetAttribute(halfkp_k_kernel,
                         cudaFuncAttributeMaxDynamicSharedMemorySize, SMEM_BYTES);

    pack_idx_kernel<<<(NNZ + 255) / 256, 256>>>(stm_idx, nstm_idx, values);

    // Main kernel with PDL: overlaps with the pack kernel.
    {
        cudaLaunchConfig_t cfg = {};
        cfg.gridDim          = dim3(FT_OUT);
        cfg.blockDim         = dim3(512);
        cfg.dynamicSmemBytes = SMEM_BYTES;
        cfg.stream           = 0;
        cudaLaunchAttribute at[1];
        at[0].id = cudaLaunchAttributeProgrammaticStreamSerialization;
        at[0].val.programmaticStreamSerializationAllowed = 1;
        cfg.attrs    = at;
        cfg.numAttrs = 1;
        cudaLaunchKernelEx(&cfg, halfkp_k_kernel,
                           ft_w, ft_b, fft_w, fft_b, out_w);
    }

    // Reduce with PDL: launches early, parks in grid-sync.
    {
        cudaLaunchConfig_t cfg = {};
        cfg.gridDim  = dim3(B_SZ / 32);
        cfg.blockDim = dim3(256);
        cfg.stream   = 0;
        cudaLaunchAttribute at[1];
        at[0].id = cudaLaunchAttributeProgrammaticStreamSerialization;
        at[0].val.programmaticStreamSerializationAllowed = 1;
        cfg.attrs    = at;
        cfg.numAttrs = 1;
        cudaLaunchKernelEx(&cfg, halfkp_reduce_kernel, out_b, out);
    }
}

// round 11
// speedup vs baseline: 1.5814x; 1.5814x over previous
#include <cuda_runtime.h>
#include <cuda_fp16.h>

#define B_SZ    512
#define FEATS   30
#define NNZ     (B_SZ * FEATS)
#define FT_OUT  512
#define N_FEAT  40960
#define N_VFEAT 640
#define KPAIRS  (FT_OUT / 2)    // 256

// Packed indices, feature-major: g_packed[f*B + b] = stm_col | (nstm_col<<16)
__device__ unsigned g_packed[NNZ];
__device__ __half   g_vals[NNZ];          // values, feature-major, fp16
// Partial outputs, [k][b] layout -> coalesced stores and reads. 1 MB.
__device__ float    g_partial[FT_OUT * B_SZ];

// Dynamic smem: __half2 sft2[N_FEAT] (pair-interleaved fused table, 160 KB),
//               __half2 sfft2[N_VFEAT] (2.5 KB)
#define SMEM_BYTES ((N_FEAT + N_VFEAT) * 4)

static __device__ __forceinline__ unsigned h2u(__half2 h) {
    return *reinterpret_cast<unsigned*>(&h);
}
static __device__ __forceinline__ __half2 u2h(unsigned u) {
    return *reinterpret_cast<__half2*>(&u);
}

// ---------------------------------------------------------------------------
// Kernel 0: prepass. Pack cols into u32, values into fp16, feature-major.
// Triggers PDL completion immediately so the main kernel streams concurrently.
// ---------------------------------------------------------------------------
__global__ void __launch_bounds__(256) pack_idx_kernel(
    const int*   __restrict__ stm_idx,    // [2, NNZ]; cols at offset NNZ
    const int*   __restrict__ nstm_idx,   // [2, NNZ]
    const float* __restrict__ values)     // [NNZ]
{
    cudaTriggerProgrammaticLaunchCompletion();

    const int e = blockIdx.x * 256 + threadIdx.x;
    if (e >= NNZ) return;
    const int b = e / FEATS;
    const int f = e % FEATS;
    const unsigned cs = (unsigned)stm_idx [NNZ + e];
    const unsigned cn = (unsigned)nstm_idx[NNZ + e];
    const int dst = f * B_SZ + b;
    g_packed[dst] = cs | (cn << 16);
    g_vals[dst]   = __float2half(values[e]);
}

// ---------------------------------------------------------------------------
// Kernel 1: one CTA per k-PAIR (256 CTAs, 512 threads, 1 CTA/SM, 163KB smem).
// Phase A: fft_w rows {k0, k0+1} -> smem, pair-interleaved half2.
// Phase B: stream ft_w rows {k0, k0+1}; sft2[c] = (ft[k0][c]+fft[k0][c%640],
//          ft[k1][c]+fft[k1][c%640]) as one half2. fft offsets have period 5
//          in the stream loop -> register-cached uint4 pairs.
// (PDL grid sync before Phase C.)
// Phase C: thread t = batch row t. ONE random LDS.32 per (feature, side)
//          serves BOTH k's. Bias + clip + out_w partials for k0 and k1.
// ---------------------------------------------------------------------------
__global__ void __launch_bounds__(512, 1) halfkp_pair_kernel(
    const float* __restrict__ ft_w,      // [512, 40960]
    const float* __restrict__ ft_b,      // [512]
    const float* __restrict__ fft_w,     // [512, 640]
    const float* __restrict__ fft_b,     // [512]
    const float* __restrict__ out_w)     // [1, 1024]
{
    cudaTriggerProgrammaticLaunchCompletion();   // let reduce kernel launch

    extern __shared__ char smem_raw[];
    __half2* sft2  = reinterpret_cast<__half2*>(smem_raw);   // [N_FEAT]
    __half2* sfft2 = sft2 + N_FEAT;                          // [N_VFEAT]

    const int kp = blockIdx.x;
    const int k0 = 2 * kp;
    const int t  = threadIdx.x;

    // ---- Phase A: fft rows pair-interleaved ----
    if (t < N_VFEAT / 4) {   // 160 threads, one float4 per row each
        float4 a = __ldg(reinterpret_cast<const float4*>(
                             fft_w + (size_t)k0 * N_VFEAT) + t);
        float4 b = __ldg(reinterpret_cast<const float4*>(
                             fft_w + (size_t)(k0 + 1) * N_VFEAT) + t);
        uint4 p;
        p.x = h2u(__floats2half2_rn(a.x, b.x));
        p.y = h2u(__floats2half2_rn(a.y, b.y));
        p.z = h2u(__floats2half2_rn(a.z, b.z));
        p.w = h2u(__floats2half2_rn(a.w, b.w));
        reinterpret_cast<uint4*>(sfft2)[t] = p;
    }
    __syncthreads();

    // ---- Phase B: stream both rows, fuse fft, store pair-interleaved ----
    {
        // fft offset m_i = (4t + 2048 i) % 640 has period 5 (2048%640=128).
        // Cache the 5 distinct 16B sfft2 groups in registers.
        uint4 fc[5];
        #pragma unroll
        for (int j = 0; j < 5; j++) {
            const int m = (4 * t + 128 * j) % N_VFEAT;   // multiple of 4
            fc[j] = *reinterpret_cast<const uint4*>(sfft2 + m);
        }

        const float4* r0 = reinterpret_cast<const float4*>(
                               ft_w + (size_t)k0 * N_FEAT);
        const float4* r1 = reinterpret_cast<const float4*>(
                               ft_w + (size_t)(k0 + 1) * N_FEAT);
        #pragma unroll
        for (int i = 0; i < N_FEAT / 4 / 512; i++) {     // 20 iterations
            const int idx = t + i * 512;
            const int c   = idx * 4;                      // half2 column
            const uint4 f = fc[i % 5];                    // static per unroll
            float4 a = __ldg(r0 + idx);
            float4 b = __ldg(r1 + idx);
            uint4 p;
            p.x = h2u(__hadd2(__floats2half2_rn(a.x, b.x), u2h(f.x)));
            p.y = h2u(__hadd2(__floats2half2_rn(a.y, b.y), u2h(f.y)));
            p.z = h2u(__hadd2(__floats2half2_rn(a.z, b.z), u2h(f.z)));
            p.w = h2u(__hadd2(__floats2half2_rn(a.w, b.w), u2h(f.w)));
            *reinterpret_cast<uint4*>(sft2 + c) = p;      // STS.128 coalesced
        }
    }
    __syncthreads();

    // PDL: packed index data must be complete (and visible) before Phase C.
    cudaGridDependencySynchronize();

    // ---- Phase C: thread t = batch row t; one LDS.32 serves both k's ----
    float2 accs = make_float2(0.f, 0.f);
    float2 accn = make_float2(0.f, 0.f);

    #pragma unroll
    for (int c = 0; c < 3; c++) {                         // chunks of 10
        unsigned p[10];
        __half   v[10];
        #pragma unroll
        for (int f = 0; f < 10; f++) {
            const int idx = (c * 10 + f) * B_SZ + t;      // lane-consecutive
            p[f] = __ldg(g_packed + idx);
            v[f] = g_vals[idx];
        }
        #pragma unroll
        for (int f = 0; f < 10; f++) {
            const float vf = __half2float(v[f]);
            float2 ws = __half22float2(sft2[p[f] & 0xFFFFu]);
            float2 wn = __half22float2(sft2[p[f] >> 16]);
            accs.x = fmaf(vf, ws.x, accs.x);
            accs.y = fmaf(vf, ws.y, accs.y);
            accn.x = fmaf(vf, wn.x, accn.x);
            accn.y = fmaf(vf, wn.y, accn.y);
        }
    }

    // ---- Epilogue: bias + clip + out_w partials for k0 and k1 ----
    const float b0 = __ldg(ft_b + k0)     + __ldg(fft_b + k0);
    const float b1 = __ldg(ft_b + k0 + 1) + __ldg(fft_b + k0 + 1);
    const float w0 = __ldg(out_w + k0);
    const float w1 = __ldg(out_w + k0 + 1);
    const float u0 = __ldg(out_w + FT_OUT + k0);
    const float u1 = __ldg(out_w + FT_OUT + k0 + 1);

    g_partial[(size_t)k0 * B_SZ + t] =
        w0 * __saturatef(accs.x + b0) + u0 * __saturatef(accn.x + b0);
    g_partial[(size_t)(k0 + 1) * B_SZ + t] =
        w1 * __saturatef(accs.y + b1) + u1 * __saturatef(accn.y + b1);
}

// ---------------------------------------------------------------------------
// Kernel 2: sum the 512 k-partials per batch row ([k][b], coalesced along b),
// add out_b, sigmoid. Deterministic fixed-order summation. PDL-parked.
// ---------------------------------------------------------------------------
__global__ void __launch_bounds__(256) halfkp_reduce_kernel(
    const float* __restrict__ out_b,
    float*       __restrict__ out)       // [512]
{
    const int tx = threadIdx.x & 31;     // batch lane
    const int ty = threadIdx.x >> 5;     // k group (0..7), 64 k's each
    const int b  = blockIdx.x * 32 + tx;

    cudaGridDependencySynchronize();     // wait for main kernel's g_partial

    float s = 0.f;
    #pragma unroll 8
    for (int i = 0; i < FT_OUT / 8; i++)
        s += g_partial[(ty * (FT_OUT / 8) + i) * B_SZ + b];

    __shared__ float red[8][33];
    red[ty][tx] = s;
    __syncthreads();

    if (ty == 0) {
        float tot = __ldg(out_b);
        #pragma unroll
        for (int j = 0; j < 8; j++) tot += red[j][tx];
        out[b] = 1.0f / (1.0f + expf(-tot));
    }
}

// ---------------------------------------------------------------------------
extern "C" void kernel_launch(void* const* d_in, const int* in_sizes, int n_in,
                              void* d_out, int out_size) {
    const int*   stm_idx  = (const int*)  d_in[0];
    const int*   nstm_idx = (const int*)  d_in[1];
    const float* values   = (const float*)d_in[2];
    const float* ft_w     = (const float*)d_in[3];
    const float* ft_b     = (const float*)d_in[4];
    const float* fft_w    = (const float*)d_in[5];
    const float* fft_b    = (const float*)d_in[6];
    const float* out_w    = (const float*)d_in[7];
    const float* out_b    = (const float*)d_in[8];
    float*       out      = (float*)d_out;

    (void)in_sizes; (void)n_in; (void)out_size;

    cudaFuncSetAttribute(halfkp_pair_kernel,
                         cudaFuncAttributeMaxDynamicSharedMemorySize, SMEM_BYTES);

    pack_idx_kernel<<<(NNZ + 255) / 256, 256>>>(stm_idx, nstm_idx, values);

    // Main kernel with PDL: overlaps with the pack kernel.
    {
        cudaLaunchConfig_t cfg = {};
        cfg.gridDim          = dim3(KPAIRS);
        cfg.blockDim         = dim3(512);
        cfg.dynamicSmemBytes = SMEM_BYTES;
        cfg.stream           = 0;
        cudaLaunchAttribute at[1];
        at[0].id = cudaLaunchAttributeProgrammaticStreamSerialization;
        at[0].val.programmaticStreamSerializationAllowed = 1;
        cfg.attrs    = at;
        cfg.numAttrs = 1;
        cudaLaunchKernelEx(&cfg, halfkp_pair_kernel,
                           ft_w, ft_b, fft_w, fft_b, out_w);
    }

    // Reduce with PDL: launches early, parks in grid-sync.
    {
        cudaLaunchConfig_t cfg = {};
        cfg.gridDim  = dim3(B_SZ / 32);
        cfg.blockDim = dim3(256);
        cfg.stream   = 0;
        cudaLaunchAttribute at[1];
        at[0].id = cudaLaunchAttributeProgrammaticStreamSerialization;
        at[0].val.programmaticStreamSerializationAllowed = 1;
        cfg.attrs    = at;
        cfg.numAttrs = 1;
        cudaLaunchKernelEx(&cfg, halfkp_reduce_kernel, out_b, out);
    }
}